// round 1
// baseline (speedup 1.0000x reference)
#include <cuda_runtime.h>

#define BB 2
#define SS 2048
#define DD 1024
#define HH 16
#define DK 64
#define MROWS (BB*SS)        // 4096
#define NEGV -1000000000.0f

// -------- scratch ( __device__ globals: allowed; no runtime allocation ) ----
__device__ float g_qh[(size_t)BB*HH*SS*DK];   // 16 MB each, head layout (b,h,s,dk)
__device__ float g_kh[(size_t)BB*HH*SS*DK];
__device__ float g_vh[(size_t)BB*HH*SS*DK];
__device__ float g_ctx[(size_t)MROWS*DD];     // (b,s,d) context before W_o
// fallback scores buffer if p_attn is not part of d_out (512 MB reserved)
__device__ float g_pattn_scratch[(size_t)BB*HH*SS*SS];

// ============================================================================
// Projection GEMM: Y = X @ W^T + bias.  X:(4096,1024) W:(1024,1024,row-major e,d)
// head_layout=1 -> write to (b,h,s,dk); head_layout=0 -> write (m,e) row-major.
// 128x128 tile, BK=16, 256 threads, 8x8 per thread.
// ============================================================================
__global__ __launch_bounds__(256) void k_proj(
    const float* __restrict__ X, const float* __restrict__ W,
    const float* __restrict__ bias, float* __restrict__ Y, int head_layout)
{
    __shared__ float As[16][128];
    __shared__ float Bsm[16][128];
    const int bm = blockIdx.y * 128;
    const int bn = blockIdx.x * 128;
    const int tid = threadIdx.x;
    const int tm = (tid >> 4) << 3;
    const int tn = (tid & 15) << 3;

    float acc[8][8];
#pragma unroll
    for (int i = 0; i < 8; i++)
#pragma unroll
        for (int j = 0; j < 8; j++) acc[i][j] = 0.f;

    for (int k0 = 0; k0 < DD; k0 += 16) {
#pragma unroll
        for (int i = 0; i < 2; i++) {
            int l = tid + i * 256;
            int r = l >> 2;
            int c = (l & 3) << 2;
            float4 xa = *(const float4*)(X + (size_t)(bm + r) * DD + k0 + c);
            As[c + 0][r] = xa.x; As[c + 1][r] = xa.y;
            As[c + 2][r] = xa.z; As[c + 3][r] = xa.w;
            float4 wb = *(const float4*)(W + (size_t)(bn + r) * DD + k0 + c);
            Bsm[c + 0][r] = wb.x; Bsm[c + 1][r] = wb.y;
            Bsm[c + 2][r] = wb.z; Bsm[c + 3][r] = wb.w;
        }
        __syncthreads();
#pragma unroll
        for (int k = 0; k < 16; k++) {
            float4 a0 = *(const float4*)&As[k][tm];
            float4 a1 = *(const float4*)&As[k][tm + 4];
            float4 b0 = *(const float4*)&Bsm[k][tn];
            float4 b1 = *(const float4*)&Bsm[k][tn + 4];
            float a[8] = {a0.x, a0.y, a0.z, a0.w, a1.x, a1.y, a1.z, a1.w};
            float b[8] = {b0.x, b0.y, b0.z, b0.w, b1.x, b1.y, b1.z, b1.w};
#pragma unroll
            for (int i = 0; i < 8; i++)
#pragma unroll
                for (int j = 0; j < 8; j++)
                    acc[i][j] = fmaf(a[i], b[j], acc[i][j]);
        }
        __syncthreads();
    }

#pragma unroll
    for (int i = 0; i < 8; i++) {
        int m = bm + tm + i;
        int bb = m >> 11;
        int s  = m & (SS - 1);
#pragma unroll
        for (int j = 0; j < 8; j++) {
            int e = bn + tn + j;
            float vv = acc[i][j] + bias[e];
            if (head_layout) {
                int h  = e >> 6;
                int dk = e & 63;
                Y[(((size_t)bb * HH + h) * SS + s) * DK + dk] = vv;
            } else {
                Y[(size_t)m * DD + e] = vv;
            }
        }
    }
}

// ============================================================================
// Scores: P[z,q,k] = (Qh[z,q,:] . Kh[z,k,:]) / 8, masked. z=b*H+h.
// 128x128 tile, K=64 (BK=16 x4), 256 threads.
// ============================================================================
__global__ __launch_bounds__(256) void k_scores(
    const int* __restrict__ mask, float* __restrict__ P)
{
    __shared__ float Qs[16][128];
    __shared__ float Ks[16][128];
    const int z  = blockIdx.z;
    const int bq = blockIdx.y * 128;
    const int bk = blockIdx.x * 128;
    const float* Q  = g_qh + (size_t)z * SS * DK;
    const float* Kh = g_kh + (size_t)z * SS * DK;
    const int tid = threadIdx.x;
    const int tm = (tid >> 4) << 3;
    const int tn = (tid & 15) << 3;

    float acc[8][8];
#pragma unroll
    for (int i = 0; i < 8; i++)
#pragma unroll
        for (int j = 0; j < 8; j++) acc[i][j] = 0.f;

    for (int k0 = 0; k0 < DK; k0 += 16) {
#pragma unroll
        for (int i = 0; i < 2; i++) {
            int l = tid + i * 256;
            int r = l >> 2;
            int c = (l & 3) << 2;
            float4 qa = *(const float4*)(Q + (size_t)(bq + r) * DK + k0 + c);
            Qs[c + 0][r] = qa.x; Qs[c + 1][r] = qa.y;
            Qs[c + 2][r] = qa.z; Qs[c + 3][r] = qa.w;
            float4 ka = *(const float4*)(Kh + (size_t)(bk + r) * DK + k0 + c);
            Ks[c + 0][r] = ka.x; Ks[c + 1][r] = ka.y;
            Ks[c + 2][r] = ka.z; Ks[c + 3][r] = ka.w;
        }
        __syncthreads();
#pragma unroll
        for (int k = 0; k < 16; k++) {
            float4 a0 = *(const float4*)&Qs[k][tm];
            float4 a1 = *(const float4*)&Qs[k][tm + 4];
            float4 b0 = *(const float4*)&Ks[k][tn];
            float4 b1 = *(const float4*)&Ks[k][tn + 4];
            float a[8] = {a0.x, a0.y, a0.z, a0.w, a1.x, a1.y, a1.z, a1.w};
            float b[8] = {b0.x, b0.y, b0.z, b0.w, b1.x, b1.y, b1.z, b1.w};
#pragma unroll
            for (int i = 0; i < 8; i++)
#pragma unroll
                for (int j = 0; j < 8; j++)
                    acc[i][j] = fmaf(a[i], b[j], acc[i][j]);
        }
        __syncthreads();
    }

    const int bb = z >> 4;  // z / H
    float* Pz = P + (size_t)z * SS * SS;
#pragma unroll
    for (int i = 0; i < 8; i++) {
        int qrow = bq + tm + i;
        const int* mrow = mask + ((size_t)bb * SS + qrow) * SS + bk + tn;
        int4 m0 = *(const int4*)(mrow);
        int4 m1 = *(const int4*)(mrow + 4);
        float4 o0, o1;
        o0.x = m0.x ? acc[i][0] * 0.125f : NEGV;
        o0.y = m0.y ? acc[i][1] * 0.125f : NEGV;
        o0.z = m0.z ? acc[i][2] * 0.125f : NEGV;
        o0.w = m0.w ? acc[i][3] * 0.125f : NEGV;
        o1.x = m1.x ? acc[i][4] * 0.125f : NEGV;
        o1.y = m1.y ? acc[i][5] * 0.125f : NEGV;
        o1.z = m1.z ? acc[i][6] * 0.125f : NEGV;
        o1.w = m1.w ? acc[i][7] * 0.125f : NEGV;
        float* prow = Pz + (size_t)qrow * SS + bk + tn;
        *(float4*)(prow)     = o0;
        *(float4*)(prow + 4) = o1;
    }
}

// ============================================================================
// Row softmax in-place over 2048 cols. One block (256 thr) per row.
// ============================================================================
__global__ __launch_bounds__(256) void k_softmax(float* __restrict__ P)
{
    __shared__ float red[8];
    float* p = P + (size_t)blockIdx.x * SS;
    const int tid = threadIdx.x;

    float4 v0 = ((const float4*)p)[tid];
    float4 v1 = ((const float4*)p)[tid + 256];

    float m = fmaxf(fmaxf(fmaxf(v0.x, v0.y), fmaxf(v0.z, v0.w)),
                    fmaxf(fmaxf(v1.x, v1.y), fmaxf(v1.z, v1.w)));
#pragma unroll
    for (int o = 16; o; o >>= 1) m = fmaxf(m, __shfl_xor_sync(~0u, m, o));
    if ((tid & 31) == 0) red[tid >> 5] = m;
    __syncthreads();
    m = red[0];
#pragma unroll
    for (int i = 1; i < 8; i++) m = fmaxf(m, red[i]);
    __syncthreads();

    float4 e0, e1;
    e0.x = __expf(v0.x - m); e0.y = __expf(v0.y - m);
    e0.z = __expf(v0.z - m); e0.w = __expf(v0.w - m);
    e1.x = __expf(v1.x - m); e1.y = __expf(v1.y - m);
    e1.z = __expf(v1.z - m); e1.w = __expf(v1.w - m);
    float s = (e0.x + e0.y) + (e0.z + e0.w) + (e1.x + e1.y) + (e1.z + e1.w);
#pragma unroll
    for (int o = 16; o; o >>= 1) s += __shfl_xor_sync(~0u, s, o);
    if ((tid & 31) == 0) red[tid >> 5] = s;
    __syncthreads();
    s = red[0];
#pragma unroll
    for (int i = 1; i < 8; i++) s += red[i];
    float inv = 1.0f / s;

    e0.x *= inv; e0.y *= inv; e0.z *= inv; e0.w *= inv;
    e1.x *= inv; e1.y *= inv; e1.z *= inv; e1.w *= inv;
    ((float4*)p)[tid]       = e0;
    ((float4*)p)[tid + 256] = e1;
}

// ============================================================================
// Ctx = P @ Vh per (b,h); M=2048, N=64, K=2048.  Tile 128x64, BK=32.
// Writes ctx in (b,s,d) layout for the final projection.
// ============================================================================
__global__ __launch_bounds__(256) void k_av(const float* __restrict__ P,
                                            float* __restrict__ Ctx)
{
    __shared__ float Ps[32][128];
    __shared__ float Vs[32][64];
    const int z  = blockIdx.z;
    const int bq = blockIdx.y * 128;
    const float* Pz = P + (size_t)z * SS * SS;
    const float* V  = g_vh + (size_t)z * SS * DK;
    const int tid = threadIdx.x;
    const int tm = (tid >> 4) << 3;   // 8 rows
    const int tn = (tid & 15) << 2;   // 4 cols

    float acc[8][4];
#pragma unroll
    for (int i = 0; i < 8; i++)
#pragma unroll
        for (int j = 0; j < 4; j++) acc[i][j] = 0.f;

    for (int k0 = 0; k0 < SS; k0 += 32) {
#pragma unroll
        for (int i = 0; i < 4; i++) {          // P tile: 128x32
            int l = tid + i * 256;
            int r = l >> 3;
            int c = (l & 7) << 2;
            float4 pv = *(const float4*)(Pz + (size_t)(bq + r) * SS + k0 + c);
            Ps[c + 0][r] = pv.x; Ps[c + 1][r] = pv.y;
            Ps[c + 2][r] = pv.z; Ps[c + 3][r] = pv.w;
        }
#pragma unroll
        for (int i = 0; i < 2; i++) {          // V tile: 32x64
            int l = tid + i * 256;
            int r = l >> 4;
            int c = (l & 15) << 2;
            *(float4*)&Vs[r][c] = *(const float4*)(V + (size_t)(k0 + r) * DK + c);
        }
        __syncthreads();
#pragma unroll
        for (int k = 0; k < 32; k++) {
            float4 a0 = *(const float4*)&Ps[k][tm];
            float4 a1 = *(const float4*)&Ps[k][tm + 4];
            float4 b  = *(const float4*)&Vs[k][tn];
            float a[8] = {a0.x, a0.y, a0.z, a0.w, a1.x, a1.y, a1.z, a1.w};
            float bv[4] = {b.x, b.y, b.z, b.w};
#pragma unroll
            for (int i = 0; i < 8; i++)
#pragma unroll
                for (int j = 0; j < 4; j++)
                    acc[i][j] = fmaf(a[i], bv[j], acc[i][j]);
        }
        __syncthreads();
    }

    const int bb = z >> 4;
    const int h  = z & 15;
#pragma unroll
    for (int i = 0; i < 8; i++) {
        int qrow = bq + tm + i;
        float4 o = make_float4(acc[i][0], acc[i][1], acc[i][2], acc[i][3]);
        *(float4*)(Ctx + ((size_t)bb * SS + qrow) * DD + h * DK + tn) = o;
    }
}

// ============================================================================
extern "C" void kernel_launch(void* const* d_in, const int* in_sizes, int n_in,
                              void* d_out, int out_size)
{
    const float* q    = (const float*)d_in[0];
    const float* k    = (const float*)d_in[1];
    const float* v    = (const float*)d_in[2];
    const int*   mask = (const int*)  d_in[3];
    const float* Wq   = (const float*)d_in[4];
    const float* bq   = (const float*)d_in[5];
    const float* Wk   = (const float*)d_in[6];
    const float* bk   = (const float*)d_in[7];
    const float* Wv   = (const float*)d_in[8];
    const float* bv   = (const float*)d_in[9];
    const float* Wo   = (const float*)d_in[10];
    const float* bo   = (const float*)d_in[11];
    float* out = (float*)d_out;

    const long long out_elems = (long long)MROWS * DD;             // 4,194,304
    const long long p_elems   = (long long)BB * HH * SS * SS;      // 134,217,728

    float* p_base;
    if ((long long)out_size >= out_elems + p_elems) {
        p_base = out + out_elems;                 // p_attn lives in d_out
    } else {
        void* sp = nullptr;
        cudaGetSymbolAddress(&sp, g_pattn_scratch);
        p_base = (float*)sp;
    }

    // resolve device scratch symbols
    void *pq, *pk, *pv, *pc;
    cudaGetSymbolAddress(&pq, g_qh);
    cudaGetSymbolAddress(&pk, g_kh);
    cudaGetSymbolAddress(&pv, g_vh);
    cudaGetSymbolAddress(&pc, g_ctx);

    dim3 gProj(DD / 128, MROWS / 128);            // (8, 32)
    k_proj<<<gProj, 256>>>(q, Wq, bq, (float*)pq, 1);
    k_proj<<<gProj, 256>>>(k, Wk, bk, (float*)pk, 1);
    k_proj<<<gProj, 256>>>(v, Wv, bv, (float*)pv, 1);

    dim3 gScores(SS / 128, SS / 128, BB * HH);    // (16, 16, 32)
    k_scores<<<gScores, 256>>>(mask, p_base);

    k_softmax<<<BB * HH * SS, 256>>>(p_base);     // 65536 rows

    dim3 gAV(1, SS / 128, BB * HH);               // (1, 16, 32)
    k_av<<<gAV, 256>>>(p_base, (float*)pc);

    k_proj<<<gProj, 256>>>((const float*)pc, Wo, bo, out, 0);
}

// round 4
// speedup vs baseline: 3.2005x; 3.2005x over previous
#include <cuda_runtime.h>
#include <cuda_fp16.h>
#include <cstdint>

#define BB 2
#define SS 2048
#define DD 1024
#define HH 16
#define DK 64
#define MROWS (BB*SS)
#define NEGV -1000000000.0f

// ---------------- scratch ----------------
__device__ __align__(128) __half g_a16[(size_t)MROWS*DD];      // converted A (input or ctx)
__device__ __align__(128) __half g_w16[(size_t)DD*DD];         // converted W
__device__ __align__(128) __half g_qh16[(size_t)BB*HH*SS*DK];  // (z,s,dk) half
__device__ __align__(128) __half g_kh16[(size_t)BB*HH*SS*DK];  // (z,s,dk) half
__device__ __align__(128) __half g_vt16[(size_t)BB*HH*DK*SS];  // (z,dk,s) half
__device__ __align__(128) __half g_p16[(size_t)BB*HH*SS*SS];   // fp16 copy of p_attn
__device__ float g_pattn_scratch[(size_t)BB*HH*SS*SS];         // fallback

// ---------------- helpers ----------------
__device__ __forceinline__ uint32_t smem_u32(const void* p) {
    uint32_t a;
    asm("{ .reg .u64 t; cvta.to.shared.u64 t, %1; cvt.u32.u64 %0, t; }" : "=r"(a) : "l"(p));
    return a;
}

#define CP_ASYNC16(dst, src) \
    asm volatile("cp.async.cg.shared.global [%0], [%1], 16;" :: "r"(dst), "l"(src) : "memory")
#define CP_COMMIT() asm volatile("cp.async.commit_group;" ::: "memory")
#define CP_WAIT(n)  asm volatile("cp.async.wait_group %0;" :: "n"(n) : "memory")

__device__ __forceinline__ void ldm_x4(uint32_t addr, uint32_t& r0, uint32_t& r1,
                                       uint32_t& r2, uint32_t& r3) {
    asm volatile("ldmatrix.sync.aligned.m8n8.x4.shared.b16 {%0,%1,%2,%3}, [%4];"
                 : "=r"(r0), "=r"(r1), "=r"(r2), "=r"(r3) : "r"(addr));
}

__device__ __forceinline__ void mma16816(float* c, const uint32_t* a, const uint32_t* b) {
    asm volatile("mma.sync.aligned.m16n8k16.row.col.f32.f16.f16.f32 "
                 "{%0,%1,%2,%3},{%4,%5,%6,%7},{%8,%9},{%0,%1,%2,%3};"
                 : "+f"(c[0]), "+f"(c[1]), "+f"(c[2]), "+f"(c[3])
                 : "r"(a[0]), "r"(a[1]), "r"(a[2]), "r"(a[3]), "r"(b[0]), "r"(b[1]));
}

// load a (rows x 32) half tile (row stride ldh halves) into padded smem (80B rows)
__device__ __forceinline__ void ld_tile(uint32_t dst, const __half* g, int ldh,
                                        int rows, int tid) {
    for (int ci = tid; ci < rows * 4; ci += 256) {
        int r = ci >> 2, c = ci & 3;
        CP_ASYNC16(dst + (uint32_t)(r * 80 + c * 16), g + (size_t)r * ldh + c * 8);
    }
}

// ============================================================================
// Unified fp16 MMA GEMM.  C[BM,BN] = A[BM,K] * B[BN,K]^T   (both K-major half)
// WG_N warps in N dir (BN = WG_N*32), WMI m16-frags per warp (BM=(8/WG_N)*WMI*16)
// MODE: 0 proj->fp32 flat +bias | 1 proj->half (z,s,dk) +bias | 2 proj->half (z,dk,s) +bias
//       3 scores->fp32 masked   | 4 av->half ctx (b,s,d)
// ============================================================================
template<int WG_N, int WMI, int MODE>
__global__ __launch_bounds__(256) void tc_mm(
    const __half* __restrict__ A, int lda, size_t aZ,
    const __half* __restrict__ B, int ldb, size_t bZ,
    int K,
    const float* __restrict__ bias,
    const int*   __restrict__ mask,
    float* __restrict__ outF,
    __half* __restrict__ outH)
{
    constexpr int BN  = WG_N * 32;
    constexpr int BM  = (8 / WG_N) * WMI * 16;
    constexpr int ASZ = BM * 80;
    constexpr int BSZ = BN * 80;
    constexpr int STG = ASZ + BSZ;
    constexpr int S   = 4;

    extern __shared__ char smraw[];
    char* sm = (char*)(((uintptr_t)smraw + 127) & ~(uintptr_t)127);
    uint32_t smu = smem_u32(sm);

    const int tid  = threadIdx.x;
    const int w    = tid >> 5, lane = tid & 31;
    const int bn   = blockIdx.x * BN, bm = blockIdx.y * BM;
    const int z    = blockIdx.z;

    A += (size_t)z * aZ + (size_t)bm * lda;
    B += (size_t)z * bZ + (size_t)bn * ldb;

    const int wm = (w / WG_N) * (WMI * 16);
    const int wn = (w % WG_N) * 32;

    float acc[WMI][4][4];
#pragma unroll
    for (int mi = 0; mi < WMI; mi++)
#pragma unroll
        for (int nt = 0; nt < 4; nt++)
#pragma unroll
            for (int x = 0; x < 4; x++) acc[mi][nt][x] = 0.f;

    const int NK = K / 32;
#pragma unroll
    for (int s = 0; s < S - 1; s++) {
        if (s < NK) {
            ld_tile(smu + s * STG,       A + s * 32, lda, BM, tid);
            ld_tile(smu + s * STG + ASZ, B + s * 32, ldb, BN, tid);
        }
        CP_COMMIT();
    }

    const int rA = (lane & 7) + ((lane >> 3) & 1) * 8;   // row within 16-row frag
    const int kO = ((lane >> 4) << 3) * 2;               // byte k-offset (0 or 16B)

    for (int kt = 0; kt < NK; kt++) {
        CP_WAIT(S - 2);
        __syncthreads();
        uint32_t sA = smu + (kt % S) * STG;
        uint32_t sB = sA + ASZ;
#pragma unroll
        for (int ks = 0; ks < 2; ks++) {
            uint32_t a[WMI][4], bf[4][2];
            uint32_t kb = (uint32_t)(ks * 32 + kO);
#pragma unroll
            for (int mi = 0; mi < WMI; mi++)
                ldm_x4(sA + (uint32_t)((wm + mi * 16 + rA) * 80) + kb,
                       a[mi][0], a[mi][1], a[mi][2], a[mi][3]);
#pragma unroll
            for (int nj = 0; nj < 2; nj++) {
                uint32_t r0, r1, r2, r3;
                ldm_x4(sB + (uint32_t)((wn + nj * 16 + rA) * 80) + kb, r0, r1, r2, r3);
                bf[nj * 2 + 0][0] = r0; bf[nj * 2 + 1][0] = r1;
                bf[nj * 2 + 0][1] = r2; bf[nj * 2 + 1][1] = r3;
            }
#pragma unroll
            for (int mi = 0; mi < WMI; mi++)
#pragma unroll
                for (int nt = 0; nt < 4; nt++)
                    mma16816(acc[mi][nt], a[mi], bf[nt]);
        }
        int ns = kt + S - 1;
        if (ns < NK) {
            ld_tile(smu + (ns % S) * STG,       A + ns * 32, lda, BM, tid);
            ld_tile(smu + (ns % S) * STG + ASZ, B + ns * 32, ldb, BN, tid);
        }
        CP_COMMIT();
    }
    CP_WAIT(0);
    __syncthreads();

    // ---- stage accumulators through smem for coalesced writes ----
    float* esm = (float*)sm;
    const int er = lane >> 2, ec = (lane & 3) * 2;
#pragma unroll
    for (int mi = 0; mi < WMI; mi++)
#pragma unroll
        for (int nt = 0; nt < 4; nt++) {
            int r0 = wm + mi * 16 + er;
            int c0 = wn + nt * 8 + ec;
            *(float2*)&esm[(size_t)r0 * BN + c0]       = make_float2(acc[mi][nt][0], acc[mi][nt][1]);
            *(float2*)&esm[(size_t)(r0 + 8) * BN + c0] = make_float2(acc[mi][nt][2], acc[mi][nt][3]);
        }
    __syncthreads();

    for (int ci = tid; ci < BM * BN / 4; ci += 256) {
        int r  = ci / (BN / 4);
        int c0 = (ci % (BN / 4)) * 4;
        float4 v = *(const float4*)&esm[(size_t)r * BN + c0];
        int m = bm + r;
        if (MODE == 0) {
            int e0 = bn + c0;
            float4 o = make_float4(v.x + bias[e0], v.y + bias[e0+1],
                                   v.z + bias[e0+2], v.w + bias[e0+3]);
            *(float4*)&outF[(size_t)m * DD + e0] = o;
        } else if (MODE == 1) {
            int e0 = bn + c0;
            int h = e0 >> 6, dk0 = e0 & 63;
            int bb = m >> 11, s = m & (SS - 1);
            __half2 h0 = __floats2half2_rn(v.x + bias[e0],   v.y + bias[e0+1]);
            __half2 h1 = __floats2half2_rn(v.z + bias[e0+2], v.w + bias[e0+3]);
            __half2* dst = (__half2*)&outH[(((size_t)(bb * HH + h)) * SS + s) * DK + dk0];
            dst[0] = h0; dst[1] = h1;
        } else if (MODE == 2) {
            int e0 = bn + c0;
            int bb = m >> 11, s = m & (SS - 1);
            float vv[4] = {v.x, v.y, v.z, v.w};
#pragma unroll
            for (int j = 0; j < 4; j++) {
                int e = e0 + j;
                int h = e >> 6, dk = e & 63;
                outH[((size_t)(bb * HH + h) * DK + dk) * SS + s] = __float2half_rn(vv[j] + bias[e]);
            }
        } else if (MODE == 3) {
            int col0 = bn + c0;
            int bb = z >> 4;
            int4 mm = *(const int4*)&mask[((size_t)bb * SS + m) * SS + col0];
            float4 o;
            o.x = mm.x ? v.x * 0.125f : NEGV;
            o.y = mm.y ? v.y * 0.125f : NEGV;
            o.z = mm.z ? v.z * 0.125f : NEGV;
            o.w = mm.w ? v.w * 0.125f : NEGV;
            *(float4*)&outF[(size_t)z * SS * SS + (size_t)m * SS + col0] = o;
        } else { // MODE 4: ctx half (b,s,d)
            int bb = z >> 4, h = z & 15;
            __half2 h0 = __floats2half2_rn(v.x, v.y);
            __half2 h1 = __floats2half2_rn(v.z, v.w);
            __half2* dst = (__half2*)&outH[((size_t)bb * SS + m) * DD + h * DK + c0];
            dst[0] = h0; dst[1] = h1;
        }
    }
}

// ======================= fp32 -> fp16 convert =======================
__global__ __launch_bounds__(256) void k_f2h(const float* __restrict__ x,
                                             __half* __restrict__ y)
{
    size_t i = ((size_t)blockIdx.x * 256 + threadIdx.x) * 4;
    float4 v = *(const float4*)(x + i);
    __half2 h0 = __floats2half2_rn(v.x, v.y);
    __half2 h1 = __floats2half2_rn(v.z, v.w);
    *(__half2*)(y + i)     = h0;
    *(__half2*)(y + i + 2) = h1;
}

// ======================= softmax: fp32 in-place + fp16 copy =======================
__global__ __launch_bounds__(256) void k_softmax(float* __restrict__ P,
                                                 __half* __restrict__ P16)
{
    __shared__ float red[8];
    const size_t row = blockIdx.x;
    float* p = P + row * SS;
    __half* p16 = P16 + row * SS;
    const int tid = threadIdx.x;

    float4 v0 = ((const float4*)p)[tid];
    float4 v1 = ((const float4*)p)[tid + 256];

    float m = fmaxf(fmaxf(fmaxf(v0.x, v0.y), fmaxf(v0.z, v0.w)),
                    fmaxf(fmaxf(v1.x, v1.y), fmaxf(v1.z, v1.w)));
#pragma unroll
    for (int o = 16; o; o >>= 1) m = fmaxf(m, __shfl_xor_sync(~0u, m, o));
    if ((tid & 31) == 0) red[tid >> 5] = m;
    __syncthreads();
    m = red[0];
#pragma unroll
    for (int i = 1; i < 8; i++) m = fmaxf(m, red[i]);
    __syncthreads();

    float4 e0, e1;
    e0.x = __expf(v0.x - m); e0.y = __expf(v0.y - m);
    e0.z = __expf(v0.z - m); e0.w = __expf(v0.w - m);
    e1.x = __expf(v1.x - m); e1.y = __expf(v1.y - m);
    e1.z = __expf(v1.z - m); e1.w = __expf(v1.w - m);
    float s = (e0.x + e0.y) + (e0.z + e0.w) + (e1.x + e1.y) + (e1.z + e1.w);
#pragma unroll
    for (int o = 16; o; o >>= 1) s += __shfl_xor_sync(~0u, s, o);
    if ((tid & 31) == 0) red[tid >> 5] = s;
    __syncthreads();
    s = red[0];
#pragma unroll
    for (int i = 1; i < 8; i++) s += red[i];
    float inv = 1.0f / s;

    e0.x *= inv; e0.y *= inv; e0.z *= inv; e0.w *= inv;
    e1.x *= inv; e1.y *= inv; e1.z *= inv; e1.w *= inv;
    ((float4*)p)[tid]       = e0;
    ((float4*)p)[tid + 256] = e1;
    __half2* ph = (__half2*)p16;
    ph[tid * 2 + 0]   = __floats2half2_rn(e0.x, e0.y);
    ph[tid * 2 + 1]   = __floats2half2_rn(e0.z, e0.w);
    ph[512 + tid * 2] = __floats2half2_rn(e1.x, e1.y);
    ph[513 + tid * 2] = __floats2half2_rn(e1.z, e1.w);
}

// ======================= launch =======================
extern "C" void kernel_launch(void* const* d_in, const int* in_sizes, int n_in,
                              void* d_out, int out_size)
{
    const float* q    = (const float*)d_in[0];
    const float* k    = (const float*)d_in[1];
    const float* v    = (const float*)d_in[2];
    const int*   mask = (const int*)  d_in[3];
    const float* Wq   = (const float*)d_in[4];
    const float* bq_  = (const float*)d_in[5];
    const float* Wk   = (const float*)d_in[6];
    const float* bk_  = (const float*)d_in[7];
    const float* Wv   = (const float*)d_in[8];
    const float* bv_  = (const float*)d_in[9];
    const float* Wo   = (const float*)d_in[10];
    const float* bo_  = (const float*)d_in[11];
    float* out = (float*)d_out;

    const long long out_elems = (long long)MROWS * DD;
    const long long p_elems   = (long long)BB * HH * SS * SS;

    float* p_base;
    if ((long long)out_size >= out_elems + p_elems) {
        p_base = out + out_elems;
    } else {
        void* sp = nullptr;
        cudaGetSymbolAddress(&sp, g_pattn_scratch);
        p_base = (float*)sp;
    }

    void *pa16, *pw16, *pqh, *pkh, *pvt, *pp16;
    cudaGetSymbolAddress(&pa16, g_a16);
    cudaGetSymbolAddress(&pw16, g_w16);
    cudaGetSymbolAddress(&pqh,  g_qh16);
    cudaGetSymbolAddress(&pkh,  g_kh16);
    cudaGetSymbolAddress(&pvt,  g_vt16);
    cudaGetSymbolAddress(&pp16, g_p16);
    __half* a16 = (__half*)pa16;
    __half* w16 = (__half*)pw16;
    __half* qh16 = (__half*)pqh;
    __half* kh16 = (__half*)pkh;
    __half* vt16 = (__half*)pvt;
    __half* p16  = (__half*)pp16;

    const int SM_MAIN = 82048;   // 4 stages * (128+128)*80 + align
    const int SM_AV   = 61568;   // 4 stages * (128+64)*80 + align
    cudaFuncSetAttribute(tc_mm<4,4,0>, cudaFuncAttributeMaxDynamicSharedMemorySize, SM_MAIN);
    cudaFuncSetAttribute(tc_mm<4,4,1>, cudaFuncAttributeMaxDynamicSharedMemorySize, SM_MAIN);
    cudaFuncSetAttribute(tc_mm<4,4,2>, cudaFuncAttributeMaxDynamicSharedMemorySize, SM_MAIN);
    cudaFuncSetAttribute(tc_mm<4,4,3>, cudaFuncAttributeMaxDynamicSharedMemorySize, SM_MAIN);
    cudaFuncSetAttribute(tc_mm<2,2,4>, cudaFuncAttributeMaxDynamicSharedMemorySize, SM_AV);

    const int nIn = MROWS * DD / 1024;   // blocks for 4M-elem convert
    const int nW  = DD * DD / 1024;      // blocks for 1M-elem convert

    dim3 gProj(DD / 128, MROWS / 128, 1);       // (8,32)
    // Q projection
    k_f2h<<<nIn, 256>>>(q, a16);
    k_f2h<<<nW, 256>>>(Wq, w16);
    tc_mm<4,4,1><<<gProj, 256, SM_MAIN>>>(a16, DD, 0, w16, DD, 0, DD,
                                          bq_, nullptr, nullptr, qh16);
    // K projection
    k_f2h<<<nIn, 256>>>(k, a16);
    k_f2h<<<nW, 256>>>(Wk, w16);
    tc_mm<4,4,1><<<gProj, 256, SM_MAIN>>>(a16, DD, 0, w16, DD, 0, DD,
                                          bk_, nullptr, nullptr, kh16);
    // V projection (transposed heads)
    k_f2h<<<nIn, 256>>>(v, a16);
    k_f2h<<<nW, 256>>>(Wv, w16);
    tc_mm<4,4,2><<<gProj, 256, SM_MAIN>>>(a16, DD, 0, w16, DD, 0, DD,
                                          bv_, nullptr, nullptr, vt16);
    // scores
    dim3 gScores(SS / 128, SS / 128, BB * HH);  // (16,16,32)
    tc_mm<4,4,3><<<gScores, 256, SM_MAIN>>>(qh16, DK, (size_t)SS * DK,
                                            kh16, DK, (size_t)SS * DK, DK,
                                            nullptr, mask, p_base, nullptr);
    // softmax (+ fp16 copy)
    k_softmax<<<BB * HH * SS, 256>>>(p_base, p16);
    // attention * V -> ctx (half, into a16)
    dim3 gAV(1, SS / 128, BB * HH);             // (1,16,32)
    tc_mm<2,2,4><<<gAV, 256, SM_AV>>>(p16, SS, (size_t)SS * SS,
                                      vt16, SS, (size_t)DK * SS, SS,
                                      nullptr, nullptr, nullptr, a16);
    // output projection
    k_f2h<<<nW, 256>>>(Wo, w16);
    tc_mm<4,4,0><<<gProj, 256, SM_MAIN>>>(a16, DD, 0, w16, DD, 0, DD,
                                          bo_, nullptr, out, nullptr);
}